// round 15
// baseline (speedup 1.0000x reference)
#include <cuda_runtime.h>
#include <cuda_fp16.h>

#define S_LEN   2048
#define DMODEL  1024
#define NHEAD   16
#define HDIM    64
#define BATCH   2
#define M_ROWS  (BATCH * S_LEN)   /* 4096 */
#define BH      (BATCH * NHEAD)   /* 32 */

// Scratch (allocation-free rule: __device__ globals).
// NOTE: APK (input rows = 4096) != WPK (weight rows = 1024).
#define APK (M_ROWS * (DMODEL / 2))          /* 2,097,152 words */
#define WPK (DMODEL * (DMODEL / 2))          /*   524,288 words */
#define QKVC (BH * S_LEN * (HDIM / 2))       /* == APK */
__device__ unsigned g_Inp[3 * APK];          /* packed query/key/value */
__device__ unsigned g_QKVp[3 * QKVC];        /* packed Q,K,V headsplit */
__device__ unsigned g_Vt[BH * HDIM * (S_LEN / 2)];
__device__ unsigned g_attnP[M_ROWS * (DMODEL / 2)];
__device__ unsigned g_Wh[4 * WPK];

// ---------------------------------------------------------------------------
// helpers
// ---------------------------------------------------------------------------
__device__ __forceinline__ void mma16h(float* d, const unsigned* a, const unsigned* b) {
    asm volatile(
        "mma.sync.aligned.m16n8k16.row.col.f32.f16.f16.f32 "
        "{%0,%1,%2,%3}, {%4,%5,%6,%7}, {%8,%9}, {%0,%1,%2,%3};\n"
        : "+f"(d[0]), "+f"(d[1]), "+f"(d[2]), "+f"(d[3])
        : "r"(a[0]), "r"(a[1]), "r"(a[2]), "r"(a[3]), "r"(b[0]), "r"(b[1]));
}

__device__ __forceinline__ void ldsm4(unsigned* r, unsigned addr) {
    asm volatile(
        "ldmatrix.sync.aligned.m8n8.x4.shared.b16 {%0,%1,%2,%3}, [%4];"
        : "=r"(r[0]), "=r"(r[1]), "=r"(r[2]), "=r"(r[3]) : "r"(addr));
}

__device__ __forceinline__ unsigned hpack(float lo_k, float hi_k) {
    __half2 t = __floats2half2_rn(lo_k, hi_k);             // .x = even k (low)
    return *(unsigned*)&t;
}

__device__ __forceinline__ unsigned smem_u32(const void* p) {
    return (unsigned)__cvta_generic_to_shared(p);
}

__device__ __forceinline__ void cpa16(unsigned dst, const void* src) {
    asm volatile("cp.async.cg.shared.global [%0], [%1], 16;\n"
                 :: "r"(dst), "l"(src));
}
__device__ __forceinline__ void cpa_commit() {
    asm volatile("cp.async.commit_group;\n");
}
__device__ __forceinline__ void cpa_wait1() {
    asm volatile("cp.async.wait_group 1;\n");
}
__device__ __forceinline__ void cpa_wait0() {
    asm volatile("cp.async.wait_group 0;\n");
}

// ---------------------------------------------------------------------------
// packers (separate launches — grids sized per tensor)
// ---------------------------------------------------------------------------
__global__ __launch_bounds__(256) void pack_w_kernel(
    const float* __restrict__ W0, const float* __restrict__ W1,
    const float* __restrict__ W2, const float* __restrict__ W3,
    unsigned* __restrict__ Wh)
{
    const int by = blockIdx.y;
    const float* W = (by == 0) ? W0 : (by == 1) ? W1 : (by == 2) ? W2 : W3;
    const size_t i = (size_t)blockIdx.x * 256 + threadIdx.x;   // < WPK
    float2 v = *(const float2*)(W + i * 2);
    Wh[(size_t)by * WPK + i] = hpack(v.x, v.y);
}

__global__ __launch_bounds__(256) void pack_in_kernel(
    const float* __restrict__ q, const float* __restrict__ k,
    const float* __restrict__ v, unsigned* __restrict__ dst)
{
    const int by = blockIdx.y;
    const float* src = (by == 0) ? q : (by == 1) ? k : v;
    const size_t i = (size_t)blockIdx.x * 256 + threadIdx.x;   // < APK
    float2 val = *(const float2*)(src + i * 2);
    dst[(size_t)by * APK + i] = hpack(val.x, val.y);
}

// ---------------------------------------------------------------------------
// V transpose-pack: Vp [bh][key][32 d-words] -> Vt [bh][d][key-pair words]
// ---------------------------------------------------------------------------
__global__ __launch_bounds__(256) void vtrans_kernel(
    const unsigned* __restrict__ Vp, unsigned* __restrict__ Vt)
{
    __shared__ unsigned sT[64 * 33];
    const int t  = threadIdx.x;
    const int kt = blockIdx.x;
    const int bh = blockIdx.y;

    const unsigned* src = Vp + ((size_t)bh * S_LEN + kt * 64) * (HDIM / 2);
#pragma unroll
    for (int i = 0; i < 8; i++) {
        const int idx = t + i * 256;
        sT[(idx >> 5) * 33 + (idx & 31)] = src[idx];
    }
    __syncthreads();

    unsigned* dst = Vt + (size_t)bh * HDIM * (S_LEN / 2) + kt * 32;
#pragma unroll
    for (int i = 0; i < 8; i++) {
        const int idx = t + i * 256;
        const int kp = idx & 31;
        const int d  = idx >> 5;
        const unsigned w0 = sT[(2 * kp) * 33 + (d >> 1)];
        const unsigned w1 = sT[(2 * kp + 1) * 33 + (d >> 1)];
        dst[(size_t)d * (S_LEN / 2) + kp] =
            __byte_perm(w0, w1, (d & 1) ? 0x7632 : 0x5410);
    }
}

// ---------------------------------------------------------------------------
// Pipelined fp16 GEMM, CTA 128x256 (warp tile 64x64), BK=32, 3-stage ring.
// 256 threads, 8 warps (2Mx4N). 32 iters, 1 sync each.
// blockIdx.z selects input/weight/bias/output (fused QKV projections).
// mode 1: headsplit packed fp16 out (*scale for z==0); mode 0: flat fp32.
// ---------------------------------------------------------------------------
#define GST 20   /* row stride words: 16 data + 4 pad (ldsm conflict-free) */
#define GROWS (128 + 256)                 /* A rows + B rows per stage */
#define GSTAGE (GROWS * GST)              /* words per stage */
#define GEMM_SMEM (3 * GSTAGE * 4)        /* 92160 bytes */

__global__ __launch_bounds__(256) void gemm_pk_kernel(
    const unsigned* __restrict__ Abase, const unsigned* __restrict__ Wbase,
    const float* __restrict__ b0p, const float* __restrict__ b1p,
    const float* __restrict__ b2p, void* __restrict__ Cv,
    int mode, float scale0)
{
    extern __shared__ unsigned gs[];

    const int tid  = threadIdx.x;
    const int lane = tid & 31;
    const int wid  = tid >> 5;
    const int wm   = wid >> 2;            // 0..1 -> 64 m-rows
    const int wn   = wid & 3;             // 0..3 -> 64 n-cols
    const int g    = lane >> 2;
    const int c    = lane & 3;
    const int bm   = blockIdx.x;          // 0..31 (128 m-rows)
    const int bn   = blockIdx.y;          // 0..3  (256 n-cols)
    const int z    = blockIdx.z;

    const float* bias = (z == 0) ? b0p : (z == 1) ? b1p : b2p;
    const float scale = (z == 0) ? scale0 : 1.0f;

    const unsigned sbase = smem_u32(gs);

    const unsigned* Aglob = Abase + (size_t)z * APK + (size_t)(bm * 128) * (DMODEL / 2);
    const unsigned* Bglob = Wbase + (size_t)z * WPK + (size_t)(bn * 256) * (DMODEL / 2);

    // ldmatrix lane offsets (bytes)
    const unsigned a_off =
        ((unsigned)((wm * 64 + ((lane >> 3) & 1) * 8 + (lane & 7)) * GST
                    + (lane >> 4) * 4)) * 4u;
    const unsigned b_off =
        ((unsigned)((wn * 64 + (lane >> 4) * 8 + (lane & 7)) * GST
                    + ((lane >> 3) & 1) * 4)) * 4u;

    float acc[4][8][4];
#pragma unroll
    for (int i = 0; i < 4; i++)
#pragma unroll
        for (int j = 0; j < 8; j++)
#pragma unroll
            for (int k = 0; k < 4; k++) acc[i][j][k] = 0.f;

    // issue one 32-k stage: A 512 chunks (2/thr) + B 1024 chunks (4/thr)
    auto issue = [&](int stage, int k0w) {
        const unsigned ab = sbase + (unsigned)(stage * GSTAGE) * 4u;
        const unsigned bb = ab + (unsigned)(128 * GST) * 4u;
#pragma unroll
        for (int i = 0; i < 2; i++) {
            const int id  = tid + i * 256;          // 0..511
            const int row = id >> 2;
            const int chw = (id & 3) * 4;
            cpa16(ab + (unsigned)(row * GST + chw) * 4u,
                  Aglob + (size_t)row * (DMODEL / 2) + k0w + chw);
        }
#pragma unroll
        for (int i = 0; i < 4; i++) {
            const int id  = tid + i * 256;          // 0..1023
            const int row = id >> 2;
            const int chw = (id & 3) * 4;
            cpa16(bb + (unsigned)(row * GST + chw) * 4u,
                  Bglob + (size_t)row * (DMODEL / 2) + k0w + chw);
        }
        cpa_commit();
    };

    issue(0, 0);
    issue(1, 16);

    const int NIT = DMODEL / 32;   // 32
    for (int it = 0; it < NIT; it++) {
        const int cur = it % 3;
        if (it == NIT - 1) cpa_wait0(); else cpa_wait1();
        __syncthreads();           // also: all warps done reading stage (it+2)%3

        if (it + 2 < NIT) issue((it + 2) % 3, (it + 2) * 16);

        const unsigned ab = sbase + (unsigned)(cur * GSTAGE) * 4u;
        const unsigned bb = ab + (unsigned)(128 * GST) * 4u;

#pragma unroll
        for (int s = 0; s < 2; s++) {
            const unsigned soff = (unsigned)(s * 8) * 4u;
            unsigned ah[4][4], bf[4][4];
#pragma unroll
            for (int ma = 0; ma < 4; ma++)
                ldsm4(ah[ma], ab + a_off + soff + (unsigned)(ma * 16 * GST) * 4u);
#pragma unroll
            for (int pq = 0; pq < 4; pq++)
                ldsm4(bf[pq], bb + b_off + soff + (unsigned)(pq * 16 * GST) * 4u);
#pragma unroll
            for (int ma = 0; ma < 4; ma++)
#pragma unroll
                for (int na = 0; na < 8; na++)
                    mma16h(acc[ma][na], ah[ma], &bf[na >> 1][(na & 1) * 2]);
        }
    }

    // epilogue
#pragma unroll
    for (int ma = 0; ma < 4; ma++) {
        const int m0 = bm * 128 + wm * 64 + ma * 16 + g;
#pragma unroll
        for (int na = 0; na < 8; na++) {
            const int n  = bn * 256 + wn * 64 + na * 8 + (c << 1);
            const float b0 = bias[n], b1 = bias[n + 1];
            const float v00 = acc[ma][na][0] + b0, v01 = acc[ma][na][1] + b1;
            const float v10 = acc[ma][na][2] + b0, v11 = acc[ma][na][3] + b1;
            if (mode) {
                unsigned* Cp = (unsigned*)Cv + (size_t)z * QKVC;
                const int h = n >> 6, dw = (n & 63) >> 1;
                const int b_0 = m0 >> 11, s_0 = m0 & (S_LEN - 1);
                const int b_1 = (m0 + 8) >> 11, s_1 = (m0 + 8) & (S_LEN - 1);
                Cp[((size_t)((b_0 * NHEAD + h) * S_LEN + s_0)) * 32 + dw] =
                    hpack(scale * v00, scale * v01);
                Cp[((size_t)((b_1 * NHEAD + h) * S_LEN + s_1)) * 32 + dw] =
                    hpack(scale * v10, scale * v11);
            } else {
                float* C = (float*)Cv;
                *(float2*)&C[(size_t)m0 * DMODEL + n]       = make_float2(v00, v01);
                *(float2*)&C[(size_t)(m0 + 8) * DMODEL + n] = make_float2(v10, v11);
            }
        }
    }
}

// ---------------------------------------------------------------------------
// Flash attention, fp16 MMA + ldmatrix, register-resident P,
// 8 warps x 32 q-rows = 256 q-rows per CTA. grid = (8, BH) = 256 CTAs.
// smem: Kbuf[2], Vbuf[2] (36.9 KB).  (unchanged — round-13 proven)
// ---------------------------------------------------------------------------
#define KW 36
#define KVW (64 * KW)
#define ATTN_SMEM (4 * KVW * 4)

__global__ __launch_bounds__(256) void attn_fp16_kernel(
    const unsigned* __restrict__ Qp, const unsigned* __restrict__ Kp,
    const unsigned* __restrict__ Vt, unsigned* __restrict__ OutP)
{
    extern __shared__ unsigned smem[];

    const int tid  = threadIdx.x;
    const int lane = tid & 31;
    const int w    = tid >> 5;            // 0..7
    const int g    = lane >> 2;
    const int c    = lane & 3;
    const int qtile = blockIdx.x;         // 0..7 (256 q-rows each)
    const int bh    = blockIdx.y;

    const unsigned sbase = smem_u32(smem);
    const unsigned kbase[2] = {sbase, sbase + KVW * 4u};
    const unsigned vbase[2] = {sbase + 2u * KVW * 4u, sbase + 3u * KVW * 4u};

    const unsigned off_b =
        ((unsigned)(((lane >> 4) * 8 + (lane & 7)) * KW + ((lane >> 3) & 1) * 4)) * 4u;

    const unsigned* Kt_b = Kp + ((size_t)bh * S_LEN) * 32;
    const unsigned* Vt_b = Vt + (size_t)bh * HDIM * (S_LEN / 2);

    unsigned qa[2][4][4];
    {
        const unsigned* Qw = Qp + ((size_t)bh * S_LEN + qtile * 256 + w * 32) * 32;
#pragma unroll
        for (int mt = 0; mt < 2; mt++)
#pragma unroll
            for (int ks = 0; ks < 4; ks++) {
                qa[mt][ks][0] = Qw[(mt * 16 + g) * 32 + ks * 8 + c];
                qa[mt][ks][1] = Qw[(mt * 16 + g + 8) * 32 + ks * 8 + c];
                qa[mt][ks][2] = Qw[(mt * 16 + g) * 32 + ks * 8 + c + 4];
                qa[mt][ks][3] = Qw[(mt * 16 + g + 8) * 32 + ks * 8 + c + 4];
            }
    }

    float oacc[2][8][4];
#pragma unroll
    for (int mt = 0; mt < 2; mt++)
#pragma unroll
        for (int i = 0; i < 8; i++)
#pragma unroll
            for (int j = 0; j < 4; j++) oacc[mt][i][j] = 0.f;
    float mrow[4] = {-1e30f, -1e30f, -1e30f, -1e30f};
    float lrow[4] = {0.f, 0.f, 0.f, 0.f};

    const int NT = S_LEN / 64;

    // prologue: tile 0 into buffer 0 (512 K-chunks + 512 V-chunks)
    {
#pragma unroll
        for (int i = 0; i < 2; i++) {
            const int f = tid + i * 256;           // 0..511
            const int row = f >> 3, ch = f & 7;
            cpa16(kbase[0] + (unsigned)(row * KW + ch * 4) * 4u,
                  Kt_b + (size_t)row * 32 + ch * 4);
            cpa16(vbase[0] + (unsigned)(row * KW + ch * 4) * 4u,
                  Vt_b + (size_t)row * (S_LEN / 2) + ch * 4);
        }
        cpa_commit();
    }

    for (int kt = 0; kt < NT; kt++) {
        const int cur = kt & 1;
        if (kt + 1 < NT) {
            const int nxt = cur ^ 1;
            const unsigned* Ksrc = Kt_b + (size_t)(kt + 1) * 64 * 32;
            const unsigned* Vsrc = Vt_b + (size_t)(kt + 1) * 32;
#pragma unroll
            for (int i = 0; i < 2; i++) {
                const int f = tid + i * 256;
                const int row = f >> 3, ch = f & 7;
                cpa16(kbase[nxt] + (unsigned)(row * KW + ch * 4) * 4u,
                      Ksrc + (size_t)row * 32 + ch * 4);
                cpa16(vbase[nxt] + (unsigned)(row * KW + ch * 4) * 4u,
                      Vsrc + (size_t)row * (S_LEN / 2) + ch * 4);
            }
            cpa_commit();
            cpa_wait1();
        } else {
            cpa_wait0();
        }
        __syncthreads();

        const unsigned ks_b = kbase[cur];
        const unsigned vs_b = vbase[cur];

        // ---- S = (Q/8) @ K^T ----
        float sacc[2][8][4];
#pragma unroll
        for (int mt = 0; mt < 2; mt++)
#pragma unroll
            for (int i = 0; i < 8; i++)
#pragma unroll
                for (int j = 0; j < 4; j++) sacc[mt][i][j] = 0.f;
#pragma unroll
        for (int ks = 0; ks < 4; ks++) {
#pragma unroll
            for (int p = 0; p < 4; p++) {
                unsigned kb[4];
                ldsm4(kb, ks_b + (unsigned)(p * 16 * KW + ks * 8) * 4u + off_b);
#pragma unroll
                for (int mt = 0; mt < 2; mt++) {
                    mma16h(sacc[mt][2 * p],     qa[mt][ks], kb);
                    mma16h(sacc[mt][2 * p + 1], qa[mt][ks], kb + 2);
                }
            }
        }

        // ---- online softmax (P stays in registers) ----
        float tm[4] = {-1e30f, -1e30f, -1e30f, -1e30f};
#pragma unroll
        for (int mt = 0; mt < 2; mt++)
#pragma unroll
            for (int na = 0; na < 8; na++) {
                tm[2 * mt]     = fmaxf(tm[2 * mt],
                                       fmaxf(sacc[mt][na][0], sacc[mt][na][1]));
                tm[2 * mt + 1] = fmaxf(tm[2 * mt + 1],
                                       fmaxf(sacc[mt][na][2], sacc[mt][na][3]));
            }
        float mn[4], alpha[4];
#pragma unroll
        for (int rg = 0; rg < 4; rg++) {
            tm[rg] = fmaxf(tm[rg], __shfl_xor_sync(0xffffffffu, tm[rg], 1));
            tm[rg] = fmaxf(tm[rg], __shfl_xor_sync(0xffffffffu, tm[rg], 2));
            mn[rg] = fmaxf(mrow[rg], tm[rg]);
            alpha[rg] = __expf(mrow[rg] - mn[rg]);
            mrow[rg] = mn[rg];
        }

        float rs[4] = {0.f, 0.f, 0.f, 0.f};
#pragma unroll
        for (int mt = 0; mt < 2; mt++)
#pragma unroll
            for (int na = 0; na < 8; na++) {
                const float p0 = __expf(sacc[mt][na][0] - mn[2 * mt]);
                const float p1 = __expf(sacc[mt][na][1] - mn[2 * mt]);
                const float p2 = __expf(sacc[mt][na][2] - mn[2 * mt + 1]);
                const float p3 = __expf(sacc[mt][na][3] - mn[2 * mt + 1]);
                rs[2 * mt]     += p0 + p1;
                rs[2 * mt + 1] += p2 + p3;
                sacc[mt][na][0] = p0; sacc[mt][na][1] = p1;
                sacc[mt][na][2] = p2; sacc[mt][na][3] = p3;
            }
#pragma unroll
        for (int rg = 0; rg < 4; rg++) {
            rs[rg] += __shfl_xor_sync(0xffffffffu, rs[rg], 1);
            rs[rg] += __shfl_xor_sync(0xffffffffu, rs[rg], 2);
            lrow[rg] = lrow[rg] * alpha[rg] + rs[rg];
        }
#pragma unroll
        for (int mt = 0; mt < 2; mt++)
#pragma unroll
            for (int na = 0; na < 8; na++) {
                oacc[mt][na][0] *= alpha[2 * mt];
                oacc[mt][na][1] *= alpha[2 * mt];
                oacc[mt][na][2] *= alpha[2 * mt + 1];
                oacc[mt][na][3] *= alpha[2 * mt + 1];
            }

        // ---- O += P @ V : P fragments packed directly from registers ----
#pragma unroll
        for (int ks = 0; ks < 4; ks++) {
            unsigned pa[2][4];
#pragma unroll
            for (int mt = 0; mt < 2; mt++) {
                pa[mt][0] = hpack(sacc[mt][2 * ks][0],     sacc[mt][2 * ks][1]);
                pa[mt][1] = hpack(sacc[mt][2 * ks][2],     sacc[mt][2 * ks][3]);
                pa[mt][2] = hpack(sacc[mt][2 * ks + 1][0], sacc[mt][2 * ks + 1][1]);
                pa[mt][3] = hpack(sacc[mt][2 * ks + 1][2], sacc[mt][2 * ks + 1][3]);
            }
#pragma unroll
            for (int p = 0; p < 4; p++) {
                unsigned vb[4];
                ldsm4(vb, vs_b + (unsigned)(p * 16 * KW + ks * 8) * 4u + off_b);
#pragma unroll
                for (int mt = 0; mt < 2; mt++) {
                    mma16h(oacc[mt][2 * p],     pa[mt], vb);
                    mma16h(oacc[mt][2 * p + 1], pa[mt], vb + 2);
                }
            }
        }
        __syncthreads();   // all reads done before next tile's stores
    }

    // ---- epilogue: packed fp16 words for the O projection ----
    const int b = bh >> 4, h = bh & 15;
#pragma unroll
    for (int mt = 0; mt < 2; mt++) {
        const float inv0 = 1.f / lrow[2 * mt];
        const float inv1 = 1.f / lrow[2 * mt + 1];
        const int s0 = qtile * 256 + w * 32 + mt * 16 + g;
        unsigned* o0 = OutP + ((size_t)(b * S_LEN + s0)) * (DMODEL / 2) + h * 32;
        unsigned* o1 = o0 + (size_t)8 * (DMODEL / 2);
#pragma unroll
        for (int na = 0; na < 8; na++) {
            o0[na * 4 + c] = hpack(oacc[mt][na][0] * inv0, oacc[mt][na][1] * inv0);
            o1[na * 4 + c] = hpack(oacc[mt][na][2] * inv1, oacc[mt][na][3] * inv1);
        }
    }
}

// ---------------------------------------------------------------------------
extern "C" void kernel_launch(void* const* d_in, const int* in_sizes, int n_in,
                              void* d_out, int out_size)
{
    const float* query = (const float*)d_in[0];
    const float* key   = (const float*)d_in[1];
    const float* value = (const float*)d_in[2];
    const float* Wq = (const float*)d_in[3];
    const float* bq = (const float*)d_in[4];
    const float* Wk = (const float*)d_in[5];
    const float* bk = (const float*)d_in[6];
    const float* Wv = (const float*)d_in[7];
    const float* bv = (const float*)d_in[8];
    const float* Wo = (const float*)d_in[9];
    const float* bo = (const float*)d_in[10];
    float* out = (float*)d_out;

    unsigned *pIn, *pQKV, *pVt, *pAp, *pWh;
    cudaGetSymbolAddress((void**)&pIn, g_Inp);
    cudaGetSymbolAddress((void**)&pQKV, g_QKVp);
    cudaGetSymbolAddress((void**)&pVt, g_Vt);
    cudaGetSymbolAddress((void**)&pAp, g_attnP);
    cudaGetSymbolAddress((void**)&pWh, g_Wh);

    static int smem_set = 0;
    if (!smem_set) {
        cudaFuncSetAttribute(attn_fp16_kernel,
                             cudaFuncAttributeMaxDynamicSharedMemorySize,
                             ATTN_SMEM);
        cudaFuncSetAttribute(gemm_pk_kernel,
                             cudaFuncAttributeMaxDynamicSharedMemorySize,
                             GEMM_SMEM);
        smem_set = 1;
    }

    // pack weights (WPK-sized grid) and inputs (APK-sized grid) separately
    dim3 pwgrid(WPK / 256, 4);
    pack_w_kernel<<<pwgrid, 256>>>(Wq, Wk, Wv, Wo, pWh);
    dim3 pigrid(APK / 256, 3);
    pack_in_kernel<<<pigrid, 256>>>(query, key, value, pIn);

    // fused Q/K/V projections: CTA 128x256, grid.z selects tensor set
    dim3 ggrid3(M_ROWS / 128, DMODEL / 256, 3);
    gemm_pk_kernel<<<ggrid3, 256, GEMM_SMEM>>>(
        pIn, pWh, bq, bk, bv, pQKV, 1, 0.125f);

    dim3 vgrid(S_LEN / 64, BH);
    vtrans_kernel<<<vgrid, 256>>>(pQKV + 2 * (size_t)QKVC, pVt);

    dim3 agrid(S_LEN / 256, BH);
    attn_fp16_kernel<<<agrid, 256, ATTN_SMEM>>>(
        pQKV, pQKV + 1 * (size_t)QKVC, pVt, pAp);

    // O projection (z=0 path; mode 0: plain fp32 output)
    dim3 ggrid1(M_ROWS / 128, DMODEL / 256, 1);
    gemm_pk_kernel<<<ggrid1, 256, GEMM_SMEM>>>(
        pAp, pWh + 3 * (size_t)WPK, bo, bo, bo, out, 0, 1.0f);
}

// round 16
// speedup vs baseline: 1.1099x; 1.1099x over previous
#include <cuda_runtime.h>
#include <cuda_fp16.h>

#define S_LEN   2048
#define DMODEL  1024
#define NHEAD   16
#define HDIM    64
#define BATCH   2
#define M_ROWS  (BATCH * S_LEN)   /* 4096 */
#define BH      (BATCH * NHEAD)   /* 32 */

// Scratch (allocation-free rule: __device__ globals).
// NOTE: APK (input rows = 4096) != WPK (weight rows = 1024).
#define APK (M_ROWS * (DMODEL / 2))          /* 2,097,152 words */
#define WPK (DMODEL * (DMODEL / 2))          /*   524,288 words */
#define QKVC (BH * S_LEN * (HDIM / 2))       /* == APK */
__device__ unsigned g_Inp[3 * APK];          /* packed query/key/value */
__device__ unsigned g_QKVp[3 * QKVC];        /* packed Q,K,V headsplit */
__device__ unsigned g_Vt[BH * HDIM * (S_LEN / 2)];
__device__ unsigned g_attnP[M_ROWS * (DMODEL / 2)];
__device__ unsigned g_Wh[4 * WPK];

#define LOG2E 1.44269504088896f

// ---------------------------------------------------------------------------
// helpers
// ---------------------------------------------------------------------------
__device__ __forceinline__ void mma16h(float* d, const unsigned* a, const unsigned* b) {
    asm volatile(
        "mma.sync.aligned.m16n8k16.row.col.f32.f16.f16.f32 "
        "{%0,%1,%2,%3}, {%4,%5,%6,%7}, {%8,%9}, {%0,%1,%2,%3};\n"
        : "+f"(d[0]), "+f"(d[1]), "+f"(d[2]), "+f"(d[3])
        : "r"(a[0]), "r"(a[1]), "r"(a[2]), "r"(a[3]), "r"(b[0]), "r"(b[1]));
}

__device__ __forceinline__ void ldsm4(unsigned* r, unsigned addr) {
    asm volatile(
        "ldmatrix.sync.aligned.m8n8.x4.shared.b16 {%0,%1,%2,%3}, [%4];"
        : "=r"(r[0]), "=r"(r[1]), "=r"(r[2]), "=r"(r[3]) : "r"(addr));
}

__device__ __forceinline__ unsigned hpack(float lo_k, float hi_k) {
    __half2 t = __floats2half2_rn(lo_k, hi_k);             // .x = even k (low)
    return *(unsigned*)&t;
}

__device__ __forceinline__ unsigned smem_u32(const void* p) {
    return (unsigned)__cvta_generic_to_shared(p);
}

__device__ __forceinline__ void cpa16(unsigned dst, const void* src) {
    asm volatile("cp.async.cg.shared.global [%0], [%1], 16;\n"
                 :: "r"(dst), "l"(src));
}
__device__ __forceinline__ void cpa_commit() {
    asm volatile("cp.async.commit_group;\n");
}
__device__ __forceinline__ void cpa_wait1() {
    asm volatile("cp.async.wait_group 1;\n");
}
__device__ __forceinline__ void cpa_wait0() {
    asm volatile("cp.async.wait_group 0;\n");
}

// ---------------------------------------------------------------------------
// packers (separate launches — grids sized per tensor)
// ---------------------------------------------------------------------------
__global__ __launch_bounds__(256) void pack_w_kernel(
    const float* __restrict__ W0, const float* __restrict__ W1,
    const float* __restrict__ W2, const float* __restrict__ W3,
    unsigned* __restrict__ Wh)
{
    const int by = blockIdx.y;
    const float* W = (by == 0) ? W0 : (by == 1) ? W1 : (by == 2) ? W2 : W3;
    const size_t i = (size_t)blockIdx.x * 256 + threadIdx.x;   // < WPK
    float2 v = *(const float2*)(W + i * 2);
    Wh[(size_t)by * WPK + i] = hpack(v.x, v.y);
}

__global__ __launch_bounds__(256) void pack_in_kernel(
    const float* __restrict__ q, const float* __restrict__ k,
    const float* __restrict__ v, unsigned* __restrict__ dst)
{
    const int by = blockIdx.y;
    const float* src = (by == 0) ? q : (by == 1) ? k : v;
    const size_t i = (size_t)blockIdx.x * 256 + threadIdx.x;   // < APK
    float2 val = *(const float2*)(src + i * 2);
    dst[(size_t)by * APK + i] = hpack(val.x, val.y);
}

// ---------------------------------------------------------------------------
// V transpose-pack: Vp [bh][key][32 d-words] -> Vt [bh][d][key-pair words]
// ---------------------------------------------------------------------------
__global__ __launch_bounds__(256) void vtrans_kernel(
    const unsigned* __restrict__ Vp, unsigned* __restrict__ Vt)
{
    __shared__ unsigned sT[64 * 33];
    const int t  = threadIdx.x;
    const int kt = blockIdx.x;
    const int bh = blockIdx.y;

    const unsigned* src = Vp + ((size_t)bh * S_LEN + kt * 64) * (HDIM / 2);
#pragma unroll
    for (int i = 0; i < 8; i++) {
        const int idx = t + i * 256;
        sT[(idx >> 5) * 33 + (idx & 31)] = src[idx];
    }
    __syncthreads();

    unsigned* dst = Vt + (size_t)bh * HDIM * (S_LEN / 2) + kt * 32;
#pragma unroll
    for (int i = 0; i < 8; i++) {
        const int idx = t + i * 256;
        const int kp = idx & 31;
        const int d  = idx >> 5;
        const unsigned w0 = sT[(2 * kp) * 33 + (d >> 1)];
        const unsigned w1 = sT[(2 * kp + 1) * 33 + (d >> 1)];
        dst[(size_t)d * (S_LEN / 2) + kp] =
            __byte_perm(w0, w1, (d & 1) ? 0x7632 : 0x5410);
    }
}

// ---------------------------------------------------------------------------
// Pipelined fp16 GEMM (round-13 proven config): CTA 128x128, BK=64,
// ldmatrix fragments, 3-stage cp.async ring, 16 iters, 1 sync each.
// blockIdx.z selects input/weight/bias/output (fused QKV projections).
// mode 1: headsplit packed fp16 out (*scale per z); mode 0: flat fp32.
// ---------------------------------------------------------------------------
#define GST 36   /* row stride words: 32 data + 4 pad (ldsm conflict-free) */
#define GSTAGE (2 * 128 * GST)            /* words per stage (A then B) */
#define GEMM_SMEM (3 * GSTAGE * 4)        /* 110592 bytes */

__global__ __launch_bounds__(256) void gemm_pk_kernel(
    const unsigned* __restrict__ Abase, const unsigned* __restrict__ Wbase,
    const float* __restrict__ b0p, const float* __restrict__ b1p,
    const float* __restrict__ b2p, void* __restrict__ Cv,
    int mode, float scale0)
{
    extern __shared__ unsigned gs[];

    const int tid  = threadIdx.x;
    const int lane = tid & 31;
    const int wid  = tid >> 5;
    const int wm   = wid >> 2;
    const int wn   = wid & 3;
    const int g    = lane >> 2;
    const int c    = lane & 3;
    const int bm   = blockIdx.x;
    const int bn   = blockIdx.y;
    const int z    = blockIdx.z;

    const float* bias = (z == 0) ? b0p : (z == 1) ? b1p : b2p;
    const float scale = (z == 0) ? scale0 : 1.0f;

    const unsigned sbase = smem_u32(gs);

    const unsigned* Aglob = Abase + (size_t)z * APK + (size_t)(bm * 128) * (DMODEL / 2);
    const unsigned* Bglob = Wbase + (size_t)z * WPK + (size_t)(bn * 128) * (DMODEL / 2);

    // ldmatrix lane offsets (bytes)
    const unsigned a_off =
        ((unsigned)((wm * 64 + ((lane >> 3) & 1) * 8 + (lane & 7)) * GST
                    + (lane >> 4) * 4)) * 4u;
    const unsigned b_off =
        ((unsigned)((wn * 32 + (lane >> 4) * 8 + (lane & 7)) * GST
                    + ((lane >> 3) & 1) * 4)) * 4u;

    float acc[4][4][4];
#pragma unroll
    for (int i = 0; i < 4; i++)
#pragma unroll
        for (int j = 0; j < 4; j++)
#pragma unroll
            for (int k = 0; k < 4; k++) acc[i][j][k] = 0.f;

    // issue one 64-k stage: A 1024 chunks + B 1024 chunks, 8 per thread
    auto issue = [&](int stage, int k0w) {
        const unsigned ab = sbase + (unsigned)(stage * GSTAGE) * 4u;
        const unsigned bb = ab + (unsigned)(128 * GST) * 4u;
#pragma unroll
        for (int i = 0; i < 4; i++) {
            const int id  = tid + i * 256;          // 0..1023
            const int row = id >> 3;
            const int chw = (id & 7) * 4;
            cpa16(ab + (unsigned)(row * GST + chw) * 4u,
                  Aglob + (size_t)row * (DMODEL / 2) + k0w + chw);
            cpa16(bb + (unsigned)(row * GST + chw) * 4u,
                  Bglob + (size_t)row * (DMODEL / 2) + k0w + chw);
        }
        cpa_commit();
    };

    issue(0, 0);
    issue(1, 32);

    const int NIT = DMODEL / 64;   // 16
    for (int it = 0; it < NIT; it++) {
        const int cur = it % 3;
        if (it == NIT - 1) cpa_wait0(); else cpa_wait1();
        __syncthreads();           // also: all warps done reading stage (it+2)%3

        if (it + 2 < NIT) issue((it + 2) % 3, (it + 2) * 32);

        const unsigned ab = sbase + (unsigned)(cur * GSTAGE) * 4u;
        const unsigned bb = ab + (unsigned)(128 * GST) * 4u;

#pragma unroll
        for (int s = 0; s < 4; s++) {
            const unsigned soff = (unsigned)(s * 8) * 4u;
            unsigned ah[4][4], bf[2][4];
#pragma unroll
            for (int ma = 0; ma < 4; ma++)
                ldsm4(ah[ma], ab + a_off + soff + (unsigned)(ma * 16 * GST) * 4u);
#pragma unroll
            for (int pq = 0; pq < 2; pq++)
                ldsm4(bf[pq], bb + b_off + soff + (unsigned)(pq * 16 * GST) * 4u);
#pragma unroll
            for (int ma = 0; ma < 4; ma++)
#pragma unroll
                for (int na = 0; na < 4; na++)
                    mma16h(acc[ma][na], ah[ma], &bf[na >> 1][(na & 1) * 2]);
        }
    }

    // epilogue
#pragma unroll
    for (int ma = 0; ma < 4; ma++) {
        const int m0 = bm * 128 + wm * 64 + ma * 16 + g;
#pragma unroll
        for (int na = 0; na < 4; na++) {
            const int n  = bn * 128 + wn * 32 + na * 8 + (c << 1);
            const float b0 = bias[n], b1 = bias[n + 1];
            const float v00 = acc[ma][na][0] + b0, v01 = acc[ma][na][1] + b1;
            const float v10 = acc[ma][na][2] + b0, v11 = acc[ma][na][3] + b1;
            if (mode) {
                unsigned* Cp = (unsigned*)Cv + (size_t)z * QKVC;
                const int h = n >> 6, dw = (n & 63) >> 1;
                const int b_0 = m0 >> 11, s_0 = m0 & (S_LEN - 1);
                const int b_1 = (m0 + 8) >> 11, s_1 = (m0 + 8) & (S_LEN - 1);
                Cp[((size_t)((b_0 * NHEAD + h) * S_LEN + s_0)) * 32 + dw] =
                    hpack(scale * v00, scale * v01);
                Cp[((size_t)((b_1 * NHEAD + h) * S_LEN + s_1)) * 32 + dw] =
                    hpack(scale * v10, scale * v11);
            } else {
                float* C = (float*)Cv;
                *(float2*)&C[(size_t)m0 * DMODEL + n]       = make_float2(v00, v01);
                *(float2*)&C[(size_t)(m0 + 8) * DMODEL + n] = make_float2(v10, v11);
            }
        }
    }
}

// ---------------------------------------------------------------------------
// Flash attention, fp16 MMA + ldmatrix, register-resident P,
// 8 warps x 32 q-rows = 256 q-rows per CTA, grid (8, BH).
// 128-key smem tiles (two 64-key compute passes per tile) -> 16 pipeline iters.
// exp2-domain softmax: Q pre-scaled by 0.125*log2(e); p = 2^(s-m).
// smem: K 2x(128x36), V 2x(64x68) = 70 KB.
// ---------------------------------------------------------------------------
#define KW 36                  /* K row stride (words) */
#define VW 68                  /* V row stride (words): 64 data + 4 pad */
#define KBUF (128 * KW)        /* words per K buffer */
#define VBUF (64 * VW)         /* words per V buffer */
#define ATTN_SMEM ((2 * KBUF + 2 * VBUF) * 4)   /* 71680 bytes */

__global__ __launch_bounds__(256) void attn_fp16_kernel(
    const unsigned* __restrict__ Qp, const unsigned* __restrict__ Kp,
    const unsigned* __restrict__ Vt, unsigned* __restrict__ OutP)
{
    extern __shared__ unsigned smem[];

    const int tid  = threadIdx.x;
    const int lane = tid & 31;
    const int w    = tid >> 5;            // 0..7
    const int g    = lane >> 2;
    const int c    = lane & 3;
    const int qtile = blockIdx.x;         // 0..7 (256 q-rows each)
    const int bh    = blockIdx.y;

    const unsigned sbase = smem_u32(smem);
    const unsigned kbase[2] = {sbase, sbase + KBUF * 4u};
    const unsigned vbase[2] = {sbase + 2u * KBUF * 4u,
                               sbase + 2u * KBUF * 4u + VBUF * 4u};

    // ldmatrix lane offsets
    const unsigned off_bk =
        ((unsigned)(((lane >> 4) * 8 + (lane & 7)) * KW + ((lane >> 3) & 1) * 4)) * 4u;
    const unsigned off_bv =
        ((unsigned)(((lane >> 4) * 8 + (lane & 7)) * VW + ((lane >> 3) & 1) * 4)) * 4u;

    const unsigned* Kt_b = Kp + ((size_t)bh * S_LEN) * 32;
    const unsigned* Vt_b = Vt + (size_t)bh * HDIM * (S_LEN / 2);

    unsigned qa[2][4][4];
    {
        const unsigned* Qw = Qp + ((size_t)bh * S_LEN + qtile * 256 + w * 32) * 32;
#pragma unroll
        for (int mt = 0; mt < 2; mt++)
#pragma unroll
            for (int ks = 0; ks < 4; ks++) {
                qa[mt][ks][0] = Qw[(mt * 16 + g) * 32 + ks * 8 + c];
                qa[mt][ks][1] = Qw[(mt * 16 + g + 8) * 32 + ks * 8 + c];
                qa[mt][ks][2] = Qw[(mt * 16 + g) * 32 + ks * 8 + c + 4];
                qa[mt][ks][3] = Qw[(mt * 16 + g + 8) * 32 + ks * 8 + c + 4];
            }
    }

    float oacc[2][8][4];
#pragma unroll
    for (int mt = 0; mt < 2; mt++)
#pragma unroll
        for (int i = 0; i < 8; i++)
#pragma unroll
            for (int j = 0; j < 4; j++) oacc[mt][i][j] = 0.f;
    float mrow[4] = {-1e30f, -1e30f, -1e30f, -1e30f};
    float lrow[4] = {0.f, 0.f, 0.f, 0.f};

    const int NT = S_LEN / 128;   // 16

    // issue one 128-key tile: K 1024 chunks (4/thr) + V 1024 chunks (4/thr)
    auto issue_tile = [&](int buf, int kt) {
        const unsigned* Ksrc = Kt_b + (size_t)kt * 128 * 32;
        const unsigned* Vsrc = Vt_b + (size_t)kt * 64;
#pragma unroll
        for (int i = 0; i < 4; i++) {
            const int id  = tid + i * 256;          // 0..1023
            const int krow = id >> 3, kch = (id & 7) * 4;
            cpa16(kbase[buf] + (unsigned)(krow * KW + kch) * 4u,
                  Ksrc + (size_t)krow * 32 + kch);
            const int vrow = id >> 4, vch = (id & 15) * 4;
            cpa16(vbase[buf] + (unsigned)(vrow * VW + vch) * 4u,
                  Vsrc + (size_t)vrow * (S_LEN / 2) + vch);
        }
        cpa_commit();
    };

    issue_tile(0, 0);

    for (int kt = 0; kt < NT; kt++) {
        const int cur = kt & 1;
        if (kt + 1 < NT) {
            issue_tile(cur ^ 1, kt + 1);
            cpa_wait1();
        } else {
            cpa_wait0();
        }
        __syncthreads();

        // two 64-key compute passes over this 128-key tile
#pragma unroll
        for (int hhalf = 0; hhalf < 2; hhalf++) {
            const unsigned ks_b = kbase[cur] + (unsigned)(hhalf * 64 * KW) * 4u;
            const unsigned vs_b = vbase[cur] + (unsigned)(hhalf * 32) * 4u;

            // ---- S = (Q * 0.125*log2e) @ K^T ----
            float sacc[2][8][4];
#pragma unroll
            for (int mt = 0; mt < 2; mt++)
#pragma unroll
                for (int i = 0; i < 8; i++)
#pragma unroll
                    for (int j = 0; j < 4; j++) sacc[mt][i][j] = 0.f;
#pragma unroll
            for (int ks = 0; ks < 4; ks++) {
#pragma unroll
                for (int p = 0; p < 4; p++) {
                    unsigned kb[4];
                    ldsm4(kb, ks_b + (unsigned)(p * 16 * KW + ks * 8) * 4u + off_bk);
#pragma unroll
                    for (int mt = 0; mt < 2; mt++) {
                        mma16h(sacc[mt][2 * p],     qa[mt][ks], kb);
                        mma16h(sacc[mt][2 * p + 1], qa[mt][ks], kb + 2);
                    }
                }
            }

            // ---- online softmax in log2 domain ----
            float tm[4] = {-1e30f, -1e30f, -1e30f, -1e30f};
#pragma unroll
            for (int mt = 0; mt < 2; mt++)
#pragma unroll
                for (int na = 0; na < 8; na++) {
                    tm[2 * mt]     = fmaxf(tm[2 * mt],
                                           fmaxf(sacc[mt][na][0], sacc[mt][na][1]));
                    tm[2 * mt + 1] = fmaxf(tm[2 * mt + 1],
                                           fmaxf(sacc[mt][na][2], sacc[mt][na][3]));
                }
            float mn[4], alpha[4];
#pragma unroll
            for (int rg = 0; rg < 4; rg++) {
                tm[rg] = fmaxf(tm[rg], __shfl_xor_sync(0xffffffffu, tm[rg], 1));
                tm[rg] = fmaxf(tm[rg], __shfl_xor_sync(0xffffffffu, tm[rg], 2));
                mn[rg] = fmaxf(mrow[rg], tm[rg]);
                alpha[rg] = exp2f(mrow[rg] - mn[rg]);
                mrow[rg] = mn[rg];
            }

            float rs[4] = {0.f, 0.f, 0.f, 0.f};
#pragma unroll
            for (int mt = 0; mt < 2; mt++)
#pragma unroll
                for (int na = 0; na < 8; na++) {
                    const float p0 = exp2f(sacc[mt][na][0] - mn[2 * mt]);
                    const float p1 = exp2f(sacc[mt][na][1] - mn[2 * mt]);
                    const float p2 = exp2f(sacc[mt][na][2] - mn[2 * mt + 1]);
                    const float p3 = exp2f(sacc[mt][na][3] - mn[2 * mt + 1]);
                    rs[2 * mt]     += p0 + p1;
                    rs[2 * mt + 1] += p2 + p3;
                    sacc[mt][na][0] = p0; sacc[mt][na][1] = p1;
                    sacc[mt][na][2] = p2; sacc[mt][na][3] = p3;
                }
#pragma unroll
            for (int rg = 0; rg < 4; rg++) {
                rs[rg] += __shfl_xor_sync(0xffffffffu, rs[rg], 1);
                rs[rg] += __shfl_xor_sync(0xffffffffu, rs[rg], 2);
                lrow[rg] = lrow[rg] * alpha[rg] + rs[rg];
            }
#pragma unroll
            for (int mt = 0; mt < 2; mt++)
#pragma unroll
                for (int na = 0; na < 8; na++) {
                    oacc[mt][na][0] *= alpha[2 * mt];
                    oacc[mt][na][1] *= alpha[2 * mt];
                    oacc[mt][na][2] *= alpha[2 * mt + 1];
                    oacc[mt][na][3] *= alpha[2 * mt + 1];
                }

            // ---- O += P @ V : P fragments packed from registers ----
#pragma unroll
            for (int ks = 0; ks < 4; ks++) {
                unsigned pa[2][4];
#pragma unroll
                for (int mt = 0; mt < 2; mt++) {
                    pa[mt][0] = hpack(sacc[mt][2 * ks][0],     sacc[mt][2 * ks][1]);
                    pa[mt][1] = hpack(sacc[mt][2 * ks][2],     sacc[mt][2 * ks][3]);
                    pa[mt][2] = hpack(sacc[mt][2 * ks + 1][0], sacc[mt][2 * ks + 1][1]);
                    pa[mt][3] = hpack(sacc[mt][2 * ks + 1][2], sacc[mt][2 * ks + 1][3]);
                }
#pragma unroll
                for (int p = 0; p < 4; p++) {
                    unsigned vb[4];
                    ldsm4(vb, vs_b + (unsigned)(p * 16 * VW + ks * 8) * 4u + off_bv);
#pragma unroll
                    for (int mt = 0; mt < 2; mt++) {
                        mma16h(oacc[mt][2 * p],     pa[mt], vb);
                        mma16h(oacc[mt][2 * p + 1], pa[mt], vb + 2);
                    }
                }
            }
        }
        __syncthreads();   // all reads done before next tile's stores
    }

    // ---- epilogue: packed fp16 words for the O projection ----
    const int b = bh >> 4, h = bh & 15;
#pragma unroll
    for (int mt = 0; mt < 2; mt++) {
        const float inv0 = 1.f / lrow[2 * mt];
        const float inv1 = 1.f / lrow[2 * mt + 1];
        const int s0 = qtile * 256 + w * 32 + mt * 16 + g;
        unsigned* o0 = OutP + ((size_t)(b * S_LEN + s0)) * (DMODEL / 2) + h * 32;
        unsigned* o1 = o0 + (size_t)8 * (DMODEL / 2);
#pragma unroll
        for (int na = 0; na < 8; na++) {
            o0[na * 4 + c] = hpack(oacc[mt][na][0] * inv0, oacc[mt][na][1] * inv0);
            o1[na * 4 + c] = hpack(oacc[mt][na][2] * inv1, oacc[mt][na][3] * inv1);
        }
    }
}

// ---------------------------------------------------------------------------
extern "C" void kernel_launch(void* const* d_in, const int* in_sizes, int n_in,
                              void* d_out, int out_size)
{
    const float* query = (const float*)d_in[0];
    const float* key   = (const float*)d_in[1];
    const float* value = (const float*)d_in[2];
    const float* Wq = (const float*)d_in[3];
    const float* bq = (const float*)d_in[4];
    const float* Wk = (const float*)d_in[5];
    const float* bk = (const float*)d_in[6];
    const float* Wv = (const float*)d_in[7];
    const float* bv = (const float*)d_in[8];
    const float* Wo = (const float*)d_in[9];
    const float* bo = (const float*)d_in[10];
    float* out = (float*)d_out;

    unsigned *pIn, *pQKV, *pVt, *pAp, *pWh;
    cudaGetSymbolAddress((void**)&pIn, g_Inp);
    cudaGetSymbolAddress((void**)&pQKV, g_QKVp);
    cudaGetSymbolAddress((void**)&pVt, g_Vt);
    cudaGetSymbolAddress((void**)&pAp, g_attnP);
    cudaGetSymbolAddress((void**)&pWh, g_Wh);

    static int smem_set = 0;
    if (!smem_set) {
        cudaFuncSetAttribute(attn_fp16_kernel,
                             cudaFuncAttributeMaxDynamicSharedMemorySize,
                             ATTN_SMEM);
        cudaFuncSetAttribute(gemm_pk_kernel,
                             cudaFuncAttributeMaxDynamicSharedMemorySize,
                             GEMM_SMEM);
        smem_set = 1;
    }

    // pack weights (WPK-sized grid) and inputs (APK-sized grid) separately
    dim3 pwgrid(WPK / 256, 4);
    pack_w_kernel<<<pwgrid, 256>>>(Wq, Wk, Wv, Wo, pWh);
    dim3 pigrid(APK / 256, 3);
    pack_in_kernel<<<pigrid, 256>>>(query, key, value, pIn);

    // fused Q/K/V projections: grid.z selects tensor set.
    // Q scale folds softmax 1/sqrt(64) AND log2(e) for exp2-domain softmax.
    dim3 ggrid3(M_ROWS / 128, DMODEL / 128, 3);
    gemm_pk_kernel<<<ggrid3, 256, GEMM_SMEM>>>(
        pIn, pWh, bq, bk, bv, pQKV, 1, 0.125f * LOG2E);

    dim3 vgrid(S_LEN / 64, BH);
    vtrans_kernel<<<vgrid, 256>>>(pQKV + 2 * (size_t)QKVC, pVt);

    dim3 agrid(S_LEN / 256, BH);
    attn_fp16_kernel<<<agrid, 256, ATTN_SMEM>>>(
        pQKV, pQKV + 1 * (size_t)QKVC, pVt, pAp);

    // O projection (z=0 path; mode 0: plain fp32 output)
    dim3 ggrid1(M_ROWS / 128, DMODEL / 128, 1);
    gemm_pk_kernel<<<ggrid1, 256, GEMM_SMEM>>>(
        pAp, pWh + 3 * (size_t)WPK, bo, bo, bo, out, 0, 1.0f);
}